// round 4
// baseline (speedup 1.0000x reference)
#include <cuda_runtime.h>
#include <math.h>

// ---- problem constants ----
#define BB   8
#define CC   384
#define LL   1024
#define NHH  8
#define DKK  48
#define DVV  48
#define CFF_ 1536
#define NBIAS_ 3969
#define LN_EPS_ 1e-5f

typedef unsigned long long u64;

// ---- packed fp32x2 helpers (Blackwell FFMA2 path) ----
__device__ __forceinline__ u64 fma2(u64 a, u64 b, u64 c) {
    u64 d;
    asm("fma.rn.f32x2 %0, %1, %2, %3;" : "=l"(d) : "l"(a), "l"(b), "l"(c));
    return d;
}
__device__ __forceinline__ u64 mul2(u64 a, u64 b) {
    u64 d;
    asm("mul.rn.f32x2 %0, %1, %2;" : "=l"(d) : "l"(a), "l"(b));
    return d;
}
__device__ __forceinline__ u64 pack2(float lo, float hi) {
    u64 d;
    asm("mov.b64 %0, {%1, %2};" : "=l"(d) : "f"(lo), "f"(hi));
    return d;
}
__device__ __forceinline__ float2 unpack2(u64 v) {
    float lo, hi;
    asm("mov.b64 {%0, %1}, %2;" : "=f"(lo), "=f"(hi) : "l"(v));
    return make_float2(lo, hi);
}

// ---- scratch ----
__device__ float g_tok [BB*LL*CC];
__device__ float g_q   [BB*NHH*LL*DKK];
__device__ float g_k   [BB*NHH*LL*DKK];
__device__ float g_v   [BB*NHH*LL*DKK];
__device__ float g_attn[BB*LL*NHH*DVV];
__device__ float g_ytok[BB*LL*CC];
__device__ float g_u1  [BB*LL*CFF_];

// ============================================================
// LayerNorm (unchanged)
// ============================================================
__global__ void ln_kernel(const float* __restrict__ x,
                          const float* __restrict__ gamma,
                          const float* __restrict__ beta,
                          float* __restrict__ tok)
{
    int b  = blockIdx.y;
    int l0 = blockIdx.x * 32;
    int lane = threadIdx.x;
    int cy   = threadIdx.y;

    __shared__ float redS [8][32];
    __shared__ float redS2[8][32];
    __shared__ float s_mu[32], s_inv[32];
    __shared__ float buf[64][33];

    float s = 0.f, s2 = 0.f;
    for (int c = cy; c < CC; c += 8) {
        float v = x[((size_t)b*CC + c)*LL + l0 + lane];
        s += v; s2 += v*v;
    }
    redS[cy][lane] = s; redS2[cy][lane] = s2;
    __syncthreads();
    if (cy == 0) {
        float ts = 0.f, ts2 = 0.f;
        #pragma unroll
        for (int i = 0; i < 8; i++) { ts += redS[i][lane]; ts2 += redS2[i][lane]; }
        float mu = ts * (1.0f/384.0f);
        float var = ts2 * (1.0f/384.0f) - mu*mu;
        s_mu[lane] = mu;
        s_inv[lane] = rsqrtf(var + LN_EPS_);
    }
    __syncthreads();

    int tid = cy*32 + lane;
    for (int c0 = 0; c0 < CC; c0 += 64) {
        for (int e = tid; e < 64*32; e += 256) {
            int c = e >> 5, t = e & 31;
            buf[c][t] = x[((size_t)b*CC + c0 + c)*LL + l0 + t];
        }
        __syncthreads();
        for (int e = tid; e < 64*32; e += 256) {
            int c = e & 63, t = e >> 6;
            float v = (buf[c][t] - s_mu[t]) * s_inv[t];
            tok[((size_t)b*LL + l0 + t)*CC + c0 + c] =
                v * gamma[c0 + c] + beta[c0 + c];
        }
        __syncthreads();
    }
}

// ============================================================
// GEMM with packed f32x2 mainloop.
// Out = A[M,K] * W[N,K]^T (+bias). 128x64 tile, 256 thr, 8x4/thread.
// Accumulators pack row pairs (2ip, 2ip+1) per column j.
// ============================================================
template<int MODE>
__global__ __launch_bounds__(256)
void gemm128(const float* __restrict__ A,
             const float* __restrict__ W,
             const float* __restrict__ bias,
             float* __restrict__ Out,
             int M, int N, int K,
             const float* __restrict__ aux)
{
    __shared__ __align__(16) float As[16][132];
    __shared__ __align__(16) float Bs[16][68];

    const int tid = threadIdx.x;
    const int m0 = blockIdx.y * 128;
    const int n0 = blockIdx.x * 64;
    const int tx = tid & 15;
    const int ty = tid >> 4;

    const int ra = tid >> 1, ka = (tid & 1) * 8;
    const int nb = tid >> 2, kb = (tid & 3) * 4;

    const float* Ap = A + (size_t)(m0 + ra) * K + ka;
    const float* Wp = W + (size_t)(n0 + nb) * K + kb;

    float4 a0 = *(const float4*)Ap;
    float4 a1 = *(const float4*)(Ap + 4);
    float4 b0 = *(const float4*)Wp;

    u64 acc2[4][4];   // [row-pair][col], each packs rows (2ip, 2ip+1)
    #pragma unroll
    for (int i = 0; i < 4; i++)
        #pragma unroll
        for (int j = 0; j < 4; j++) acc2[i][j] = 0ull;

    for (int k0 = 0; k0 < K; k0 += 16) {
        As[ka+0][ra] = a0.x; As[ka+1][ra] = a0.y;
        As[ka+2][ra] = a0.z; As[ka+3][ra] = a0.w;
        As[ka+4][ra] = a1.x; As[ka+5][ra] = a1.y;
        As[ka+6][ra] = a1.z; As[ka+7][ra] = a1.w;
        Bs[kb+0][nb] = b0.x; Bs[kb+1][nb] = b0.y;
        Bs[kb+2][nb] = b0.z; Bs[kb+3][nb] = b0.w;
        __syncthreads();

        if (k0 + 16 < K) {
            Ap += 16; Wp += 16;
            a0 = *(const float4*)Ap;
            a1 = *(const float4*)(Ap + 4);
            b0 = *(const float4*)Wp;
        }

        #pragma unroll
        for (int kk = 0; kk < 16; kk++) {
            // A row pairs: 8 contiguous floats = 4 packed b64
            ulonglong2 ap0 = *(const ulonglong2*)&As[kk][ty*8];
            ulonglong2 ap1 = *(const ulonglong2*)&As[kk][ty*8 + 4];
            u64 ap[4] = {ap0.x, ap0.y, ap1.x, ap1.y};
            float4 bv = *(const float4*)&Bs[kk][tx*4];
            u64 b2[4] = {pack2(bv.x, bv.x), pack2(bv.y, bv.y),
                         pack2(bv.z, bv.z), pack2(bv.w, bv.w)};
            #pragma unroll
            for (int i = 0; i < 4; i++)
                #pragma unroll
                for (int j = 0; j < 4; j++)
                    acc2[i][j] = fma2(ap[i], b2[j], acc2[i][j]);
        }
        __syncthreads();
    }

    #pragma unroll
    for (int ip = 0; ip < 4; ip++) {
        #pragma unroll
        for (int half = 0; half < 2; half++) {
            int i = ip*2 + half;
            int row = m0 + ty*8 + i;
            int b = row >> 10, l = row & 1023;
            #pragma unroll
            for (int j = 0; j < 4; j++) {
                float2 pr = unpack2(acc2[ip][j]);
                float vacc = half ? pr.y : pr.x;
                int col = n0 + tx*4 + j;
                float v = vacc + (bias ? bias[col] : 0.f);
                if (MODE == 1) {
                    Out[(size_t)row * N + col] =
                        0.5f * v * (1.0f + erff(v * 0.70710678118654752f));
                } else if (MODE == 2) {
                    int h = col / 48, d = col % 48;
                    Out[(size_t)(((b*8 + h) * 1024) + l) * 48 + d] = v;
                } else if (MODE == 3) {
                    Out[(size_t)row * 384 + col] =
                        v + aux[(size_t)(b*384 + col) * 1024 + l];
                } else { // MODE 4
                    Out[(size_t)(b*384 + col) * 1024 + l] =
                        v + aux[(size_t)row * 384 + col];
                }
            }
        }
    }
}

// ============================================================
// Flash attention v3: f32x2 packed dot products.
// Scores reduce over d (both operands contiguous -> packed free).
// PV reduces over mm (both operands contiguous -> packed free).
// ============================================================
#define QT 64
#define MC 64

__global__ __launch_bounds__(256)
void attn_kernel(const float* __restrict__ q,
                 const float* __restrict__ k,
                 const float* __restrict__ v,
                 const float* __restrict__ rel_bias,
                 float* __restrict__ attn_out)
{
    int b  = blockIdx.y >> 3;
    int h  = blockIdx.y & 7;
    int q0 = blockIdx.x * QT;
    int tid = threadIdx.x;
    int tx = tid & 15;
    int ty = tid >> 4;

    __shared__ __align__(16) float sq[QT][48];
    __shared__ __align__(16) float sKV[64*52];      // K[64][52] / V^T[48][68]
    __shared__ __align__(16) float sP[QT][MC];
    __shared__ float sM[QT], sSum[QT];

    #define SK(m,d)  sKV[(m)*52 + (d)]
    #define SVT(d,m) sKV[(d)*68 + (m)]

    const float* qbase = &q[(size_t)((b*NHH + h) * LL) * DKK];
    const float* kbase = &k[(size_t)((b*NHH + h) * LL) * DKK];
    const float* vbase = &v[(size_t)((b*NHH + h) * LL) * DKK];
    const float* biasrow = &rel_bias[(size_t)h * NBIAS_];

    for (int e = tid; e < QT*48; e += 256)
        sq[e / 48][e % 48] = qbase[(size_t)(q0 + e/48) * 48 + (e % 48)];
    if (tid < QT) { sM[tid] = -1e30f; sSum[tid] = 0.f; }
    __syncthreads();

    const int m4 = tx * 4;
    const int d3 = tx * 3;
    u64 oacc2[4][3];     // packed partial sums over mm (even, odd)
    #pragma unroll
    for (int i = 0; i < 4; i++)
        #pragma unroll
        for (int c = 0; c < 3; c++) oacc2[i][c] = 0ull;

    for (int m0 = 0; m0 < LL; m0 += MC) {
        // ---- phase 1: stage K ----
        for (int e = tid; e < MC*48; e += 256) {
            int r = e / 48, c = e % 48;
            SK(r, c) = kbase[(size_t)(m0 + r) * 48 + c];
        }
        __syncthreads();

        // ---- phase 2: packed scores + register softmax ----
        u64 s2[4][4];
        #pragma unroll
        for (int i = 0; i < 4; i++)
            #pragma unroll
            for (int j = 0; j < 4; j++) s2[i][j] = 0ull;

        #pragma unroll
        for (int d4 = 0; d4 < 48; d4 += 4) {
            ulonglong2 qa[4];
            #pragma unroll
            for (int i = 0; i < 4; i++)
                qa[i] = *(const ulonglong2*)&sq[ty + 16*i][d4];
            #pragma unroll
            for (int j = 0; j < 4; j++) {
                ulonglong2 kv = *(const ulonglong2*)&SK(m4 + j, d4);
                #pragma unroll
                for (int i = 0; i < 4; i++) {
                    s2[i][j] = fma2(qa[i].x, kv.x, s2[i][j]);
                    s2[i][j] = fma2(qa[i].y, kv.y, s2[i][j]);
                }
            }
        }

        float al[4];
        #pragma unroll
        for (int i = 0; i < 4; i++) {
            int r = ty + 16*i;
            int l = q0 + r;
            int ly = l >> 5, lx = l & 31;
            float mo = sM[r];
            float so = sSum[r];

            float s[4];
            float rmax = -1e30f;
            #pragma unroll
            for (int j = 0; j < 4; j++) {
                float2 pr = unpack2(s2[i][j]);
                int m = m0 + m4 + j;
                int idx = ((m >> 5) - ly + 32) * 32 + ((m & 31) - lx + 32);
                s[j] = pr.x + pr.y + biasrow[idx];
                rmax = fmaxf(rmax, s[j]);
            }
            #pragma unroll
            for (int o = 8; o > 0; o >>= 1)
                rmax = fmaxf(rmax, __shfl_xor_sync(0xffffffffu, rmax, o));

            float nm = fmaxf(mo, rmax);
            float rs = 0.f;
            #pragma unroll
            for (int j = 0; j < 4; j++) {
                float p = __expf(s[j] - nm);
                s[j] = p;
                rs += p;
            }
            #pragma unroll
            for (int o = 8; o > 0; o >>= 1)
                rs += __shfl_xor_sync(0xffffffffu, rs, o);

            al[i] = __expf(mo - nm);
            if (tx == 0) {
                sM[r]   = nm;
                sSum[r] = so * al[i] + rs;
            }
            float4 pv = make_float4(s[0], s[1], s[2], s[3]);
            *(float4*)&sP[r][m4] = pv;
        }
        __syncthreads();

        // ---- phase 3: stage V^T ----
        for (int e = tid; e < MC*48; e += 256) {
            int r = e / 48, c = e % 48;
            SVT(c, r) = vbase[(size_t)(m0 + r) * 48 + c];
        }
        __syncthreads();

        // ---- phase 4: packed PV ----
        #pragma unroll
        for (int i = 0; i < 4; i++) {
            u64 al2 = pack2(al[i], al[i]);
            #pragma unroll
            for (int c = 0; c < 3; c++)
                oacc2[i][c] = mul2(oacc2[i][c], al2);
        }

        #pragma unroll 4
        for (int mm = 0; mm < MC; mm += 4) {
            ulonglong2 p[4];
            #pragma unroll
            for (int i = 0; i < 4; i++)
                p[i] = *(const ulonglong2*)&sP[ty + 16*i][mm];
            #pragma unroll
            for (int c = 0; c < 3; c++) {
                ulonglong2 vv = *(const ulonglong2*)&SVT(d3 + c, mm);
                #pragma unroll
                for (int i = 0; i < 4; i++) {
                    oacc2[i][c] = fma2(p[i].x, vv.x, oacc2[i][c]);
                    oacc2[i][c] = fma2(p[i].y, vv.y, oacc2[i][c]);
                }
            }
        }
        __syncthreads();
    }

    #pragma unroll
    for (int i = 0; i < 4; i++) {
        int r = ty + 16*i;
        float invs = 1.0f / sSum[r];
        #pragma unroll
        for (int c = 0; c < 3; c++) {
            float2 pr = unpack2(oacc2[i][c]);
            attn_out[(size_t)(b*LL + q0 + r) * (NHH*DVV) + h*DVV + d3 + c] =
                (pr.x + pr.y) * invs;
        }
    }
}

// ============================================================
// launch
// ============================================================
extern "C" void kernel_launch(void* const* d_in, const int* in_sizes, int n_in,
                              void* d_out, int out_size)
{
    (void)in_sizes; (void)n_in; (void)out_size;
    const float* x        = (const float*)d_in[0];
    const float* gamma    = (const float*)d_in[1];
    const float* beta     = (const float*)d_in[2];
    const float* Wq       = (const float*)d_in[3];
    const float* Wk       = (const float*)d_in[4];
    const float* Wv       = (const float*)d_in[5];
    const float* Wo       = (const float*)d_in[6];
    const float* bo       = (const float*)d_in[7];
    const float* rel_bias = (const float*)d_in[8];
    const float* fc1_w    = (const float*)d_in[9];
    const float* fc1_b    = (const float*)d_in[10];
    const float* fc2_w    = (const float*)d_in[11];
    const float* fc2_b    = (const float*)d_in[12];
    float* out = (float*)d_out;

    float *tok, *q, *k, *v, *attn, *ytok, *u1;
    cudaGetSymbolAddress((void**)&tok,  g_tok);
    cudaGetSymbolAddress((void**)&q,    g_q);
    cudaGetSymbolAddress((void**)&k,    g_k);
    cudaGetSymbolAddress((void**)&v,    g_v);
    cudaGetSymbolAddress((void**)&attn, g_attn);
    cudaGetSymbolAddress((void**)&ytok, g_ytok);
    cudaGetSymbolAddress((void**)&u1,   g_u1);

    const int M = BB * LL;

    ln_kernel<<<dim3(LL/32, BB), dim3(32, 8)>>>(x, gamma, beta, tok);

    gemm128<2><<<dim3(384/64,  M/128), 256>>>(tok, Wq, nullptr, q, M, 384, 384, nullptr);
    gemm128<2><<<dim3(384/64,  M/128), 256>>>(tok, Wk, nullptr, k, M, 384, 384, nullptr);
    gemm128<2><<<dim3(384/64,  M/128), 256>>>(tok, Wv, nullptr, v, M, 384, 384, nullptr);

    attn_kernel<<<dim3(LL/QT, BB*NHH), 256>>>(q, k, v, rel_bias, attn);

    gemm128<3><<<dim3(384/64,  M/128), 256>>>(attn, Wo, bo, ytok, M, 384, 384, x);
    gemm128<1><<<dim3(1536/64, M/128), 256>>>(ytok, fc1_w, fc1_b, u1, M, 1536, 384, nullptr);
    gemm128<4><<<dim3(384/64,  M/128), 256>>>(u1, fc2_w, fc2_b, out, M, 384, 1536, ytok);
}

// round 5
// speedup vs baseline: 1.5602x; 1.5602x over previous
#include <cuda_runtime.h>
#include <math.h>
#include <stdint.h>

// ---- problem constants ----
#define BB   8
#define CC   384
#define LL   1024
#define NHH  8
#define DKK  48
#define DVV  48
#define CFF_ 1536
#define NBIAS_ 3969
#define LN_EPS_ 1e-5f

// ---- scratch ----
__device__ float g_tok [BB*LL*CC];
__device__ float g_q   [BB*NHH*LL*DKK];
__device__ float g_k   [BB*NHH*LL*DKK];
__device__ float g_v   [BB*NHH*LL*DKK];
__device__ float g_attn[BB*LL*NHH*DVV];
__device__ float g_ytok[BB*LL*CC];
__device__ float g_u1  [BB*LL*CFF_];

// ---- tf32 helpers ----
__device__ __forceinline__ void tf32_split(float x, uint32_t& h, uint32_t& l) {
    asm("cvt.rna.tf32.f32 %0, %1;" : "=r"(h) : "f"(x));
    float lf = x - __uint_as_float(h);
    asm("cvt.rna.tf32.f32 %0, %1;" : "=r"(l) : "f"(lf));
}

#define MMA_TF32(c, a, b) \
    asm volatile("mma.sync.aligned.m16n8k8.row.col.f32.tf32.tf32.f32 " \
        "{%0,%1,%2,%3}, {%4,%5,%6,%7}, {%8,%9}, {%0,%1,%2,%3};" \
        : "+f"(c[0]), "+f"(c[1]), "+f"(c[2]), "+f"(c[3]) \
        : "r"(a[0]), "r"(a[1]), "r"(a[2]), "r"(a[3]), "r"(b[0]), "r"(b[1]))

// ============================================================
// LayerNorm (round-3, unchanged)
// ============================================================
__global__ void ln_kernel(const float* __restrict__ x,
                          const float* __restrict__ gamma,
                          const float* __restrict__ beta,
                          float* __restrict__ tok)
{
    int b  = blockIdx.y;
    int l0 = blockIdx.x * 32;
    int lane = threadIdx.x;
    int cy   = threadIdx.y;

    __shared__ float redS [8][32];
    __shared__ float redS2[8][32];
    __shared__ float s_mu[32], s_inv[32];
    __shared__ float buf[64][33];

    float s = 0.f, s2 = 0.f;
    for (int c = cy; c < CC; c += 8) {
        float v = x[((size_t)b*CC + c)*LL + l0 + lane];
        s += v; s2 += v*v;
    }
    redS[cy][lane] = s; redS2[cy][lane] = s2;
    __syncthreads();
    if (cy == 0) {
        float ts = 0.f, ts2 = 0.f;
        #pragma unroll
        for (int i = 0; i < 8; i++) { ts += redS[i][lane]; ts2 += redS2[i][lane]; }
        float mu = ts * (1.0f/384.0f);
        float var = ts2 * (1.0f/384.0f) - mu*mu;
        s_mu[lane] = mu;
        s_inv[lane] = rsqrtf(var + LN_EPS_);
    }
    __syncthreads();

    int tid = cy*32 + lane;
    for (int c0 = 0; c0 < CC; c0 += 64) {
        for (int e = tid; e < 64*32; e += 256) {
            int c = e >> 5, t = e & 31;
            buf[c][t] = x[((size_t)b*CC + c0 + c)*LL + l0 + t];
        }
        __syncthreads();
        for (int e = tid; e < 64*32; e += 256) {
            int c = e & 63, t = e >> 6;
            float v = (buf[c][t] - s_mu[t]) * s_inv[t];
            tok[((size_t)b*LL + l0 + t)*CC + c0 + c] =
                v * gamma[c0 + c] + beta[c0 + c];
        }
        __syncthreads();
    }
}

// ============================================================
// Tensor-core GEMM: Out = A[M,K] * W[N,K]^T (+bias), tf32x3.
// 128x64 block (256 thr, 8 warps as 4m x 2n), warp tile 32x32.
// mma.sync.m16n8k8, fp32 accum; hi/lo split for fp32-grade accuracy.
// MODE 1: GELU   MODE 2: QKV head-scatter
// MODE 3: +x residual (transposed read)  MODE 4: transposed store + residual
// ============================================================
template<int MODE>
__global__ __launch_bounds__(256)
void gemm_tc(const float* __restrict__ A,
             const float* __restrict__ W,
             const float* __restrict__ bias,
             float* __restrict__ Out,
             int M, int N, int K,
             const float* __restrict__ aux)
{
    __shared__ uint32_t Ah[16][136], Al[16][136];
    __shared__ uint32_t Bh[16][72],  Bl[16][72];

    const int tid  = threadIdx.x;
    const int m0   = blockIdx.y * 128;
    const int n0   = blockIdx.x * 64;
    const int warp = tid >> 5, lane = tid & 31;
    const int wm   = (warp >> 1) * 32;   // warp m-offset (0,32,64,96)
    const int wn   = (warp & 1) * 32;    // warp n-offset (0,32)
    const int gk   = lane & 3;           // k group
    const int gr   = lane >> 2;          // row/col group

    // staging mapping
    const int ra = tid >> 1, ka = (tid & 1) * 8;   // A: 8 floats/thread
    const int nb = tid >> 2, kb = (tid & 3) * 4;   // W: 4 floats/thread

    const float* Ap = A + (size_t)(m0 + ra) * K + ka;
    const float* Wp = W + (size_t)(n0 + nb) * K + kb;

    float4 a0 = *(const float4*)Ap;
    float4 a1 = *(const float4*)(Ap + 4);
    float4 b0 = *(const float4*)Wp;

    float acc[2][4][4];
    #pragma unroll
    for (int mi = 0; mi < 2; mi++)
        #pragma unroll
        for (int nj = 0; nj < 4; nj++)
            #pragma unroll
            for (int r = 0; r < 4; r++) acc[mi][nj][r] = 0.f;

    for (int k0 = 0; k0 < K; k0 += 16) {
        // ---- stage + split hi/lo ----
        {
            float av[8] = {a0.x, a0.y, a0.z, a0.w, a1.x, a1.y, a1.z, a1.w};
            #pragma unroll
            for (int i = 0; i < 8; i++)
                tf32_split(av[i], Ah[ka + i][ra], Al[ka + i][ra]);
            float bv[4] = {b0.x, b0.y, b0.z, b0.w};
            #pragma unroll
            for (int i = 0; i < 4; i++)
                tf32_split(bv[i], Bh[kb + i][nb], Bl[kb + i][nb]);
        }
        __syncthreads();

        if (k0 + 16 < K) {
            Ap += 16; Wp += 16;
            a0 = *(const float4*)Ap;
            a1 = *(const float4*)(Ap + 4);
            b0 = *(const float4*)Wp;
        }

        #pragma unroll
        for (int kk0 = 0; kk0 < 16; kk0 += 8) {
            uint32_t ah[2][4], al_[2][4];
            #pragma unroll
            for (int mi = 0; mi < 2; mi++) {
                int mr = wm + mi*16 + gr;
                ah[mi][0]  = Ah[kk0 + gk    ][mr];
                ah[mi][1]  = Ah[kk0 + gk    ][mr + 8];
                ah[mi][2]  = Ah[kk0 + gk + 4][mr];
                ah[mi][3]  = Ah[kk0 + gk + 4][mr + 8];
                al_[mi][0] = Al[kk0 + gk    ][mr];
                al_[mi][1] = Al[kk0 + gk    ][mr + 8];
                al_[mi][2] = Al[kk0 + gk + 4][mr];
                al_[mi][3] = Al[kk0 + gk + 4][mr + 8];
            }
            #pragma unroll
            for (int nj = 0; nj < 4; nj++) {
                int nc = wn + nj*8 + gr;
                uint32_t bh[2], bl[2];
                bh[0] = Bh[kk0 + gk    ][nc];
                bh[1] = Bh[kk0 + gk + 4][nc];
                bl[0] = Bl[kk0 + gk    ][nc];
                bl[1] = Bl[kk0 + gk + 4][nc];
                #pragma unroll
                for (int mi = 0; mi < 2; mi++) {
                    MMA_TF32(acc[mi][nj], ah[mi],  bh);
                    MMA_TF32(acc[mi][nj], al_[mi], bh);
                    MMA_TF32(acc[mi][nj], ah[mi],  bl);
                }
            }
        }
        __syncthreads();
    }

    // ---- epilogue: c0..c3 -> (gr, 2gk), (gr, 2gk+1), (gr+8, 2gk), (gr+8, 2gk+1) ----
    #pragma unroll
    for (int mi = 0; mi < 2; mi++) {
        #pragma unroll
        for (int nj = 0; nj < 4; nj++) {
            #pragma unroll
            for (int r = 0; r < 4; r++) {
                int row = m0 + wm + mi*16 + gr + ((r >> 1) ? 8 : 0);
                int col = n0 + wn + nj*8 + 2*gk + (r & 1);
                int b = row >> 10, l = row & 1023;
                float v = acc[mi][nj][r] + (bias ? bias[col] : 0.f);
                if (MODE == 1) {
                    Out[(size_t)row * N + col] =
                        0.5f * v * (1.0f + erff(v * 0.70710678118654752f));
                } else if (MODE == 2) {
                    int h = col / 48, d = col % 48;
                    Out[(size_t)(((b*8 + h) * 1024) + l) * 48 + d] = v;
                } else if (MODE == 3) {
                    Out[(size_t)row * 384 + col] =
                        v + aux[(size_t)(b*384 + col) * 1024 + l];
                } else { // MODE 4
                    Out[(size_t)(b*384 + col) * 1024 + l] =
                        v + aux[(size_t)row * 384 + col];
                }
            }
        }
    }
}

// ============================================================
// Flash attention (round-3 version, unchanged — register softmax)
// ============================================================
#define QT 64
#define MC 64

__global__ __launch_bounds__(256)
void attn_kernel(const float* __restrict__ q,
                 const float* __restrict__ k,
                 const float* __restrict__ v,
                 const float* __restrict__ rel_bias,
                 float* __restrict__ attn_out)
{
    int b  = blockIdx.y >> 3;
    int h  = blockIdx.y & 7;
    int q0 = blockIdx.x * QT;
    int tid = threadIdx.x;
    int tx = tid & 15;
    int ty = tid >> 4;

    __shared__ __align__(16) float sq[QT][48];
    __shared__ __align__(16) float sKV[64*52];
    __shared__ __align__(16) float sP[QT][MC];
    __shared__ float sM[QT], sSum[QT];

    #define SK(m,d)  sKV[(m)*52 + (d)]
    #define SVT(d,m) sKV[(d)*68 + (m)]

    const float* qbase = &q[(size_t)((b*NHH + h) * LL) * DKK];
    const float* kbase = &k[(size_t)((b*NHH + h) * LL) * DKK];
    const float* vbase = &v[(size_t)((b*NHH + h) * LL) * DKK];
    const float* biasrow = &rel_bias[(size_t)h * NBIAS_];

    for (int e = tid; e < QT*48; e += 256)
        sq[e / 48][e % 48] = qbase[(size_t)(q0 + e/48) * 48 + (e % 48)];
    if (tid < QT) { sM[tid] = -1e30f; sSum[tid] = 0.f; }
    __syncthreads();

    const int m4 = tx * 4;
    const int d3 = tx * 3;
    float oacc[4][3];
    #pragma unroll
    for (int i = 0; i < 4; i++)
        #pragma unroll
        for (int c = 0; c < 3; c++) oacc[i][c] = 0.f;

    for (int m0 = 0; m0 < LL; m0 += MC) {
        for (int e = tid; e < MC*48; e += 256) {
            int r = e / 48, c = e % 48;
            SK(r, c) = kbase[(size_t)(m0 + r) * 48 + c];
        }
        __syncthreads();

        float s[4][4];
        #pragma unroll
        for (int i = 0; i < 4; i++)
            #pragma unroll
            for (int j = 0; j < 4; j++) s[i][j] = 0.f;

        #pragma unroll
        for (int d4 = 0; d4 < 48; d4 += 4) {
            float4 qa[4];
            #pragma unroll
            for (int i = 0; i < 4; i++)
                qa[i] = *(const float4*)&sq[ty + 16*i][d4];
            #pragma unroll
            for (int j = 0; j < 4; j++) {
                float4 kv = *(const float4*)&SK(m4 + j, d4);
                #pragma unroll
                for (int i = 0; i < 4; i++)
                    s[i][j] += qa[i].x*kv.x + qa[i].y*kv.y
                             + qa[i].z*kv.z + qa[i].w*kv.w;
            }
        }

        float al[4];
        #pragma unroll
        for (int i = 0; i < 4; i++) {
            int r = ty + 16*i;
            int l = q0 + r;
            int ly = l >> 5, lx = l & 31;
            float mo = sM[r];
            float so = sSum[r];

            float rmax = -1e30f;
            #pragma unroll
            for (int j = 0; j < 4; j++) {
                int m = m0 + m4 + j;
                int idx = ((m >> 5) - ly + 32) * 32 + ((m & 31) - lx + 32);
                s[i][j] += biasrow[idx];
                rmax = fmaxf(rmax, s[i][j]);
            }
            #pragma unroll
            for (int o = 8; o > 0; o >>= 1)
                rmax = fmaxf(rmax, __shfl_xor_sync(0xffffffffu, rmax, o));

            float nm = fmaxf(mo, rmax);
            float rs = 0.f;
            #pragma unroll
            for (int j = 0; j < 4; j++) {
                float p = __expf(s[i][j] - nm);
                s[i][j] = p;
                rs += p;
            }
            #pragma unroll
            for (int o = 8; o > 0; o >>= 1)
                rs += __shfl_xor_sync(0xffffffffu, rs, o);

            al[i] = __expf(mo - nm);
            if (tx == 0) {
                sM[r]   = nm;
                sSum[r] = so * al[i] + rs;
            }
            float4 pv = make_float4(s[i][0], s[i][1], s[i][2], s[i][3]);
            *(float4*)&sP[r][m4] = pv;
        }
        __syncthreads();

        for (int e = tid; e < MC*48; e += 256) {
            int r = e / 48, c = e % 48;
            SVT(c, r) = vbase[(size_t)(m0 + r) * 48 + c];
        }
        __syncthreads();

        #pragma unroll
        for (int i = 0; i < 4; i++)
            #pragma unroll
            for (int c = 0; c < 3; c++) oacc[i][c] *= al[i];

        #pragma unroll 4
        for (int mm = 0; mm < MC; mm += 4) {
            float4 p[4];
            #pragma unroll
            for (int i = 0; i < 4; i++)
                p[i] = *(const float4*)&sP[ty + 16*i][mm];
            #pragma unroll
            for (int c = 0; c < 3; c++) {
                float4 vv = *(const float4*)&SVT(d3 + c, mm);
                #pragma unroll
                for (int i = 0; i < 4; i++)
                    oacc[i][c] += p[i].x*vv.x + p[i].y*vv.y
                                + p[i].z*vv.z + p[i].w*vv.w;
            }
        }
        __syncthreads();
    }

    #pragma unroll
    for (int i = 0; i < 4; i++) {
        int r = ty + 16*i;
        float invs = 1.0f / sSum[r];
        #pragma unroll
        for (int c = 0; c < 3; c++)
            attn_out[(size_t)(b*LL + q0 + r) * (NHH*DVV) + h*DVV + d3 + c] =
                oacc[i][c] * invs;
    }
}

// ============================================================
// launch
// ============================================================
extern "C" void kernel_launch(void* const* d_in, const int* in_sizes, int n_in,
                              void* d_out, int out_size)
{
    (void)in_sizes; (void)n_in; (void)out_size;
    const float* x        = (const float*)d_in[0];
    const float* gamma    = (const float*)d_in[1];
    const float* beta     = (const float*)d_in[2];
    const float* Wq       = (const float*)d_in[3];
    const float* Wk       = (const float*)d_in[4];
    const float* Wv       = (const float*)d_in[5];
    const float* Wo       = (const float*)d_in[6];
    const float* bo       = (const float*)d_in[7];
    const float* rel_bias = (const float*)d_in[8];
    const float* fc1_w    = (const float*)d_in[9];
    const float* fc1_b    = (const float*)d_in[10];
    const float* fc2_w    = (const float*)d_in[11];
    const float* fc2_b    = (const float*)d_in[12];
    float* out = (float*)d_out;

    float *tok, *q, *k, *v, *attn, *ytok, *u1;
    cudaGetSymbolAddress((void**)&tok,  g_tok);
    cudaGetSymbolAddress((void**)&q,    g_q);
    cudaGetSymbolAddress((void**)&k,    g_k);
    cudaGetSymbolAddress((void**)&v,    g_v);
    cudaGetSymbolAddress((void**)&attn, g_attn);
    cudaGetSymbolAddress((void**)&ytok, g_ytok);
    cudaGetSymbolAddress((void**)&u1,   g_u1);

    const int M = BB * LL;

    ln_kernel<<<dim3(LL/32, BB), dim3(32, 8)>>>(x, gamma, beta, tok);

    gemm_tc<2><<<dim3(384/64,  M/128), 256>>>(tok, Wq, nullptr, q, M, 384, 384, nullptr);
    gemm_tc<2><<<dim3(384/64,  M/128), 256>>>(tok, Wk, nullptr, k, M, 384, 384, nullptr);
    gemm_tc<2><<<dim3(384/64,  M/128), 256>>>(tok, Wv, nullptr, v, M, 384, 384, nullptr);

    attn_kernel<<<dim3(LL/QT, BB*NHH), 256>>>(q, k, v, rel_bias, attn);

    gemm_tc<3><<<dim3(384/64,  M/128), 256>>>(attn, Wo, bo, ytok, M, 384, 384, x);
    gemm_tc<1><<<dim3(1536/64, M/128), 256>>>(ytok, fc1_w, fc1_b, u1, M, 1536, 384, nullptr);
    gemm_tc<4><<<dim3(384/64,  M/128), 256>>>(u1, fc2_w, fc2_b, out, M, 384, 1536, ytok);
}

// round 6
// speedup vs baseline: 1.8665x; 1.1963x over previous
#include <cuda_runtime.h>
#include <cuda_bf16.h>
#include <math.h>
#include <stdint.h>

// ---- problem constants ----
#define BB   8
#define CC   384
#define LL   1024
#define MM   (BB*LL)
#define NHH  8
#define DKK  48
#define DVV  48
#define CFF_ 1536
#define NBIAS_ 3969
#define LN_EPS_ 1e-5f

typedef __nv_bfloat16 bf16;

// ---- scratch ----
__device__ __align__(16) bf16  g_tok_h [MM*CC], g_tok_l [MM*CC];
__device__ __align__(16) float g_q[MM*CC], g_k[MM*CC], g_v[MM*CC];
__device__ __align__(16) bf16  g_attn_h[MM*CC], g_attn_l[MM*CC];
__device__ __align__(16) float g_ytok[MM*CC];
__device__ __align__(16) bf16  g_ytok_h[MM*CC], g_ytok_l[MM*CC];
__device__ __align__(16) bf16  g_u1_h[MM*CFF_], g_u1_l[MM*CFF_];

// weight split pool: wq, wk, wv, wo (384*384 each), fc1 (1536*384), fc2 (384*1536)
#define OFF_WQ  0
#define OFF_WK  147456
#define OFF_WV  294912
#define OFF_WO  442368
#define OFF_FC1 589824
#define OFF_FC2 1179648
#define NW_TOTAL 1769472
__device__ __align__(16) bf16 g_w_h[NW_TOTAL], g_w_l[NW_TOTAL];

__device__ __forceinline__ void bsplit(float x, bf16& h, bf16& l) {
    h = __float2bfloat16(x);
    l = __float2bfloat16(x - __bfloat162float(h));
}

#define MMA_BF16(c, a, b) \
    asm volatile("mma.sync.aligned.m16n8k16.row.col.f32.bf16.bf16.f32 " \
        "{%0,%1,%2,%3}, {%4,%5,%6,%7}, {%8,%9}, {%0,%1,%2,%3};" \
        : "+f"(c[0]), "+f"(c[1]), "+f"(c[2]), "+f"(c[3]) \
        : "r"(a[0]), "r"(a[1]), "r"(a[2]), "r"(a[3]), "r"(b[0]), "r"(b[1]))

// ============================================================
// Weight hi/lo split (runs once per launch; trivial cost)
// ============================================================
__global__ void split_kernel(const float* __restrict__ w,
                             bf16* __restrict__ h, bf16* __restrict__ l, int n)
{
    int i = blockIdx.x * 256 + threadIdx.x;
    if (i < n) bsplit(w[i], h[i], l[i]);
}

// ============================================================
// LayerNorm -> bf16 hi/lo token matrix
// ============================================================
__global__ void ln_kernel(const float* __restrict__ x,
                          const float* __restrict__ gamma,
                          const float* __restrict__ beta,
                          bf16* __restrict__ tok_h, bf16* __restrict__ tok_l)
{
    int b  = blockIdx.y;
    int l0 = blockIdx.x * 32;
    int lane = threadIdx.x;
    int cy   = threadIdx.y;

    __shared__ float redS [8][32];
    __shared__ float redS2[8][32];
    __shared__ float s_mu[32], s_inv[32];
    __shared__ float buf[64][33];

    float s = 0.f, s2 = 0.f;
    for (int c = cy; c < CC; c += 8) {
        float v = x[((size_t)b*CC + c)*LL + l0 + lane];
        s += v; s2 += v*v;
    }
    redS[cy][lane] = s; redS2[cy][lane] = s2;
    __syncthreads();
    if (cy == 0) {
        float ts = 0.f, ts2 = 0.f;
        #pragma unroll
        for (int i = 0; i < 8; i++) { ts += redS[i][lane]; ts2 += redS2[i][lane]; }
        float mu = ts * (1.0f/384.0f);
        float var = ts2 * (1.0f/384.0f) - mu*mu;
        s_mu[lane] = mu;
        s_inv[lane] = rsqrtf(var + LN_EPS_);
    }
    __syncthreads();

    int tid = cy*32 + lane;
    for (int c0 = 0; c0 < CC; c0 += 64) {
        for (int e = tid; e < 64*32; e += 256) {
            int c = e >> 5, t = e & 31;
            buf[c][t] = x[((size_t)b*CC + c0 + c)*LL + l0 + t];
        }
        __syncthreads();
        for (int e = tid; e < 64*32; e += 256) {
            int c = e & 63, t = e >> 6;
            float v = (buf[c][t] - s_mu[t]) * s_inv[t];
            v = v * gamma[c0 + c] + beta[c0 + c];
            size_t idx = ((size_t)b*LL + l0 + t)*CC + c0 + c;
            bf16 hh, ll;
            bsplit(v, hh, ll);
            tok_h[idx] = hh; tok_l[idx] = ll;
        }
        __syncthreads();
    }
}

// ============================================================
// bf16x3 tensor-core GEMM: Out = A[M,K] * W[N,K]^T (+bias).
// A, W pre-split into bf16 hi/lo. 128x64 block, 8 warps (4m x 2n),
// warp tile 32x32, mma.m16n8k16, fp32 accum, BK=32.
// MODE 1: GELU -> outH/outL       MODE 2: QKV head-scatter (fp32)
// MODE 3: +x residual -> fp32 Out AND outH/outL
// MODE 4: transposed store + residual (final fp32 output)
// ============================================================
template<int MODE>
__global__ __launch_bounds__(256)
void gemm_bf(const bf16* __restrict__ Ah, const bf16* __restrict__ Al,
             const bf16* __restrict__ Wh, const bf16* __restrict__ Wl,
             const float* __restrict__ bias,
             float* __restrict__ Out,
             int M, int N, int K,
             const float* __restrict__ aux,
             bf16* __restrict__ outH, bf16* __restrict__ outL)
{
    __shared__ uint32_t sAh[128][20], sAl[128][20];
    __shared__ uint32_t sBh[64][20],  sBl[64][20];

    const int tid  = threadIdx.x;
    const int m0   = blockIdx.y * 128;
    const int n0   = blockIdx.x * 64;
    const int warp = tid >> 5, lane = tid & 31;
    const int wm   = (warp >> 1) * 32;
    const int wn   = (warp & 1) * 32;
    const int gk   = lane & 3;
    const int gr   = lane >> 2;

    // staging mapping (bf16 element indices)
    const int ar = tid >> 1, ak = (tid & 1) * 16;
    const int br = tid >> 2, bk = (tid & 3) * 8;

    const bf16* ApH = Ah + (size_t)(m0 + ar) * K + ak;
    const bf16* ApL = Al + (size_t)(m0 + ar) * K + ak;
    const bf16* BpH = Wh + (size_t)(n0 + br) * K + bk;
    const bf16* BpL = Wl + (size_t)(n0 + br) * K + bk;

    uint4 pah0 = *(const uint4*)ApH;
    uint4 pah1 = *(const uint4*)(ApH + 8);
    uint4 pal0 = *(const uint4*)ApL;
    uint4 pal1 = *(const uint4*)(ApL + 8);
    uint4 pbh  = *(const uint4*)BpH;
    uint4 pbl  = *(const uint4*)BpL;

    float acc[2][4][4];
    #pragma unroll
    for (int mi = 0; mi < 2; mi++)
        #pragma unroll
        for (int nj = 0; nj < 4; nj++)
            #pragma unroll
            for (int r = 0; r < 4; r++) acc[mi][nj][r] = 0.f;

    const int acol = (tid & 1) * 8;
    const int bcol = (tid & 3) * 4;

    for (int k0 = 0; k0 < K; k0 += 32) {
        *(uint4*)&sAh[ar][acol]     = pah0;
        *(uint4*)&sAh[ar][acol + 4] = pah1;
        *(uint4*)&sAl[ar][acol]     = pal0;
        *(uint4*)&sAl[ar][acol + 4] = pal1;
        *(uint4*)&sBh[br][bcol]     = pbh;
        *(uint4*)&sBl[br][bcol]     = pbl;
        __syncthreads();

        if (k0 + 32 < K) {
            ApH += 32; ApL += 32; BpH += 32; BpL += 32;
            pah0 = *(const uint4*)ApH;
            pah1 = *(const uint4*)(ApH + 8);
            pal0 = *(const uint4*)ApL;
            pal1 = *(const uint4*)(ApL + 8);
            pbh  = *(const uint4*)BpH;
            pbl  = *(const uint4*)BpL;
        }

        #pragma unroll
        for (int ks = 0; ks < 2; ks++) {
            const int kb = ks*8 + gk;
            uint32_t ah[2][4], al_[2][4];
            #pragma unroll
            for (int mi = 0; mi < 2; mi++) {
                int mr = wm + mi*16 + gr;
                ah[mi][0]  = sAh[mr    ][kb];
                ah[mi][1]  = sAh[mr + 8][kb];
                ah[mi][2]  = sAh[mr    ][kb + 4];
                ah[mi][3]  = sAh[mr + 8][kb + 4];
                al_[mi][0] = sAl[mr    ][kb];
                al_[mi][1] = sAl[mr + 8][kb];
                al_[mi][2] = sAl[mr    ][kb + 4];
                al_[mi][3] = sAl[mr + 8][kb + 4];
            }
            #pragma unroll
            for (int nj = 0; nj < 4; nj++) {
                int nc = wn + nj*8 + gr;
                uint32_t bh[2], bl[2];
                bh[0] = sBh[nc][kb];
                bh[1] = sBh[nc][kb + 4];
                bl[0] = sBl[nc][kb];
                bl[1] = sBl[nc][kb + 4];
                #pragma unroll
                for (int mi = 0; mi < 2; mi++) {
                    MMA_BF16(acc[mi][nj], ah[mi],  bh);
                    MMA_BF16(acc[mi][nj], al_[mi], bh);
                    MMA_BF16(acc[mi][nj], ah[mi],  bl);
                }
            }
        }
        __syncthreads();
    }

    // ---- epilogue: c r -> (gr + (r&2 ? 8:0), 2gk + (r&1)) ----
    #pragma unroll
    for (int mi = 0; mi < 2; mi++) {
        #pragma unroll
        for (int nj = 0; nj < 4; nj++) {
            #pragma unroll
            for (int r = 0; r < 4; r++) {
                int row = m0 + wm + mi*16 + gr + ((r & 2) ? 8 : 0);
                int col = n0 + wn + nj*8 + 2*gk + (r & 1);
                int b = row >> 10, l = row & 1023;
                float v = acc[mi][nj][r] + (bias ? bias[col] : 0.f);
                if (MODE == 2) {
                    int h = col / 48, d = col % 48;
                    Out[(size_t)(((b*8 + h) * 1024) + l) * 48 + d] = v;
                } else if (MODE == 3) {
                    v += aux[(size_t)(b*384 + col) * 1024 + l];
                    size_t idx = (size_t)row * 384 + col;
                    Out[idx] = v;
                    bf16 hh, ll;
                    bsplit(v, hh, ll);
                    outH[idx] = hh; outL[idx] = ll;
                } else if (MODE == 1) {
                    v = 0.5f * v * (1.0f + erff(v * 0.70710678118654752f));
                    size_t idx = (size_t)row * N + col;
                    bf16 hh, ll;
                    bsplit(v, hh, ll);
                    outH[idx] = hh; outL[idx] = ll;
                } else { // MODE 4
                    Out[(size_t)(b*384 + col) * 1024 + l] =
                        v + aux[(size_t)row * 384 + col];
                }
            }
        }
    }
}

// ============================================================
// Flash attention (round-3 register-softmax) -> bf16 hi/lo output
// ============================================================
#define QT 64
#define MC 64

__global__ __launch_bounds__(256)
void attn_kernel(const float* __restrict__ q,
                 const float* __restrict__ k,
                 const float* __restrict__ v,
                 const float* __restrict__ rel_bias,
                 bf16* __restrict__ attn_h, bf16* __restrict__ attn_l)
{
    int b  = blockIdx.y >> 3;
    int h  = blockIdx.y & 7;
    int q0 = blockIdx.x * QT;
    int tid = threadIdx.x;
    int tx = tid & 15;
    int ty = tid >> 4;

    __shared__ __align__(16) float sq[QT][48];
    __shared__ __align__(16) float sKV[64*52];
    __shared__ __align__(16) float sP[QT][MC];
    __shared__ float sM[QT], sSum[QT];

    #define SK(m,d)  sKV[(m)*52 + (d)]
    #define SVT(d,m) sKV[(d)*68 + (m)]

    const float* qbase = &q[(size_t)((b*NHH + h) * LL) * DKK];
    const float* kbase = &k[(size_t)((b*NHH + h) * LL) * DKK];
    const float* vbase = &v[(size_t)((b*NHH + h) * LL) * DKK];
    const float* biasrow = &rel_bias[(size_t)h * NBIAS_];

    for (int e = tid; e < QT*48; e += 256)
        sq[e / 48][e % 48] = qbase[(size_t)(q0 + e/48) * 48 + (e % 48)];
    if (tid < QT) { sM[tid] = -1e30f; sSum[tid] = 0.f; }
    __syncthreads();

    const int m4 = tx * 4;
    const int d3 = tx * 3;
    float oacc[4][3];
    #pragma unroll
    for (int i = 0; i < 4; i++)
        #pragma unroll
        for (int c = 0; c < 3; c++) oacc[i][c] = 0.f;

    for (int m0 = 0; m0 < LL; m0 += MC) {
        for (int e = tid; e < MC*48; e += 256) {
            int r = e / 48, c = e % 48;
            SK(r, c) = kbase[(size_t)(m0 + r) * 48 + c];
        }
        __syncthreads();

        float s[4][4];
        #pragma unroll
        for (int i = 0; i < 4; i++)
            #pragma unroll
            for (int j = 0; j < 4; j++) s[i][j] = 0.f;

        #pragma unroll
        for (int d4 = 0; d4 < 48; d4 += 4) {
            float4 qa[4];
            #pragma unroll
            for (int i = 0; i < 4; i++)
                qa[i] = *(const float4*)&sq[ty + 16*i][d4];
            #pragma unroll
            for (int j = 0; j < 4; j++) {
                float4 kv = *(const float4*)&SK(m4 + j, d4);
                #pragma unroll
                for (int i = 0; i < 4; i++)
                    s[i][j] += qa[i].x*kv.x + qa[i].y*kv.y
                             + qa[i].z*kv.z + qa[i].w*kv.w;
            }
        }

        float al[4];
        #pragma unroll
        for (int i = 0; i < 4; i++) {
            int r = ty + 16*i;
            int l = q0 + r;
            int ly = l >> 5, lx = l & 31;
            float mo = sM[r];
            float so = sSum[r];

            float rmax = -1e30f;
            #pragma unroll
            for (int j = 0; j < 4; j++) {
                int m = m0 + m4 + j;
                int idx = ((m >> 5) - ly + 32) * 32 + ((m & 31) - lx + 32);
                s[i][j] += biasrow[idx];
                rmax = fmaxf(rmax, s[i][j]);
            }
            #pragma unroll
            for (int o = 8; o > 0; o >>= 1)
                rmax = fmaxf(rmax, __shfl_xor_sync(0xffffffffu, rmax, o));

            float nm = fmaxf(mo, rmax);
            float rs = 0.f;
            #pragma unroll
            for (int j = 0; j < 4; j++) {
                float p = __expf(s[i][j] - nm);
                s[i][j] = p;
                rs += p;
            }
            #pragma unroll
            for (int o = 8; o > 0; o >>= 1)
                rs += __shfl_xor_sync(0xffffffffu, rs, o);

            al[i] = __expf(mo - nm);
            if (tx == 0) {
                sM[r]   = nm;
                sSum[r] = so * al[i] + rs;
            }
            float4 pv = make_float4(s[i][0], s[i][1], s[i][2], s[i][3]);
            *(float4*)&sP[r][m4] = pv;
        }
        __syncthreads();

        for (int e = tid; e < MC*48; e += 256) {
            int r = e / 48, c = e % 48;
            SVT(c, r) = vbase[(size_t)(m0 + r) * 48 + c];
        }
        __syncthreads();

        #pragma unroll
        for (int i = 0; i < 4; i++)
            #pragma unroll
            for (int c = 0; c < 3; c++) oacc[i][c] *= al[i];

        #pragma unroll 4
        for (int mm = 0; mm < MC; mm += 4) {
            float4 p[4];
            #pragma unroll
            for (int i = 0; i < 4; i++)
                p[i] = *(const float4*)&sP[ty + 16*i][mm];
            #pragma unroll
            for (int c = 0; c < 3; c++) {
                float4 vv = *(const float4*)&SVT(d3 + c, mm);
                #pragma unroll
                for (int i = 0; i < 4; i++)
                    oacc[i][c] += p[i].x*vv.x + p[i].y*vv.y
                                + p[i].z*vv.z + p[i].w*vv.w;
            }
        }
        __syncthreads();
    }

    #pragma unroll
    for (int i = 0; i < 4; i++) {
        int r = ty + 16*i;
        float invs = 1.0f / sSum[r];
        #pragma unroll
        for (int c = 0; c < 3; c++) {
            float val = oacc[i][c] * invs;
            size_t idx = (size_t)(b*LL + q0 + r) * (NHH*DVV) + h*DVV + d3 + c;
            bf16 hh, ll;
            bsplit(val, hh, ll);
            attn_h[idx] = hh; attn_l[idx] = ll;
        }
    }
}

// ============================================================
// launch
// ============================================================
extern "C" void kernel_launch(void* const* d_in, const int* in_sizes, int n_in,
                              void* d_out, int out_size)
{
    (void)in_sizes; (void)n_in; (void)out_size;
    const float* x        = (const float*)d_in[0];
    const float* gamma    = (const float*)d_in[1];
    const float* beta     = (const float*)d_in[2];
    const float* Wq       = (const float*)d_in[3];
    const float* Wk       = (const float*)d_in[4];
    const float* Wv       = (const float*)d_in[5];
    const float* Wo       = (const float*)d_in[6];
    const float* bo       = (const float*)d_in[7];
    const float* rel_bias = (const float*)d_in[8];
    const float* fc1_w    = (const float*)d_in[9];
    const float* fc1_b    = (const float*)d_in[10];
    const float* fc2_w    = (const float*)d_in[11];
    const float* fc2_b    = (const float*)d_in[12];
    float* out = (float*)d_out;

    bf16 *tok_h, *tok_l, *attn_h, *attn_l, *ytok_h, *ytok_l, *u1_h, *u1_l, *w_h, *w_l;
    float *q, *k, *v, *ytok;
    cudaGetSymbolAddress((void**)&tok_h,  g_tok_h);
    cudaGetSymbolAddress((void**)&tok_l,  g_tok_l);
    cudaGetSymbolAddress((void**)&q,      g_q);
    cudaGetSymbolAddress((void**)&k,      g_k);
    cudaGetSymbolAddress((void**)&v,      g_v);
    cudaGetSymbolAddress((void**)&attn_h, g_attn_h);
    cudaGetSymbolAddress((void**)&attn_l, g_attn_l);
    cudaGetSymbolAddress((void**)&ytok,   g_ytok);
    cudaGetSymbolAddress((void**)&ytok_h, g_ytok_h);
    cudaGetSymbolAddress((void**)&ytok_l, g_ytok_l);
    cudaGetSymbolAddress((void**)&u1_h,   g_u1_h);
    cudaGetSymbolAddress((void**)&u1_l,   g_u1_l);
    cudaGetSymbolAddress((void**)&w_h,    g_w_h);
    cudaGetSymbolAddress((void**)&w_l,    g_w_l);

    const int M = MM;

    // weight splits (cheap, deterministic)
    split_kernel<<<(147456+255)/256, 256>>>(Wq,    w_h+OFF_WQ,  w_l+OFF_WQ,  147456);
    split_kernel<<<(147456+255)/256, 256>>>(Wk,    w_h+OFF_WK,  w_l+OFF_WK,  147456);
    split_kernel<<<(147456+255)/256, 256>>>(Wv,    w_h+OFF_WV,  w_l+OFF_WV,  147456);
    split_kernel<<<(147456+255)/256, 256>>>(Wo,    w_h+OFF_WO,  w_l+OFF_WO,  147456);
    split_kernel<<<(589824+255)/256, 256>>>(fc1_w, w_h+OFF_FC1, w_l+OFF_FC1, 589824);
    split_kernel<<<(589824+255)/256, 256>>>(fc2_w, w_h+OFF_FC2, w_l+OFF_FC2, 589824);

    ln_kernel<<<dim3(LL/32, BB), dim3(32, 8)>>>(x, gamma, beta, tok_h, tok_l);

    gemm_bf<2><<<dim3(384/64,  M/128), 256>>>(tok_h, tok_l, w_h+OFF_WQ, w_l+OFF_WQ,
                                              nullptr, q, M, 384, 384, nullptr, nullptr, nullptr);
    gemm_bf<2><<<dim3(384/64,  M/128), 256>>>(tok_h, tok_l, w_h+OFF_WK, w_l+OFF_WK,
                                              nullptr, k, M, 384, 384, nullptr, nullptr, nullptr);
    gemm_bf<2><<<dim3(384/64,  M/128), 256>>>(tok_h, tok_l, w_h+OFF_WV, w_l+OFF_WV,
                                              nullptr, v, M, 384, 384, nullptr, nullptr, nullptr);

    attn_kernel<<<dim3(LL/QT, BB*NHH), 256>>>(q, k, v, rel_bias, attn_h, attn_l);

    gemm_bf<3><<<dim3(384/64,  M/128), 256>>>(attn_h, attn_l, w_h+OFF_WO, w_l+OFF_WO,
                                              bo, ytok, M, 384, 384, x, ytok_h, ytok_l);
    gemm_bf<1><<<dim3(1536/64, M/128), 256>>>(ytok_h, ytok_l, w_h+OFF_FC1, w_l+OFF_FC1,
                                              fc1_b, nullptr, M, 1536, 384, nullptr, u1_h, u1_l);
    gemm_bf<4><<<dim3(384/64,  M/128), 256>>>(u1_h, u1_l, w_h+OFF_FC2, w_l+OFF_FC2,
                                              fc2_b, out, M, 384, 1536, ytok, nullptr, nullptr);
}

// round 8
// speedup vs baseline: 2.3299x; 1.2483x over previous
#include <cuda_runtime.h>
#include <cuda_bf16.h>
#include <math.h>
#include <stdint.h>

// ---- problem constants ----
#define BB   8
#define CC   384
#define LL   1024
#define MM   (BB*LL)
#define NHH  8
#define DKK  48
#define DVV  48
#define CFF_ 1536
#define NBIAS_ 3969
#define LN_EPS_ 1e-5f

typedef __nv_bfloat16 bf16;

// ---- scratch ----
__device__ __align__(16) bf16  g_tok_h [MM*CC], g_tok_l [MM*CC];
__device__ __align__(16) float g_qkv[3*MM*CC];              // q | k | v
__device__ __align__(16) bf16  g_attn_h[MM*CC], g_attn_l[MM*CC];
__device__ __align__(16) float g_ytok[MM*CC];
__device__ __align__(16) bf16  g_ytok_h[MM*CC], g_ytok_l[MM*CC];
__device__ __align__(16) bf16  g_u1_h[MM*CFF_], g_u1_l[MM*CFF_];

#define OFF_WQ  0
#define OFF_WK  147456
#define OFF_WV  294912
#define OFF_WO  442368
#define OFF_FC1 589824
#define OFF_FC2 1179648
#define NW_TOTAL 1769472
__device__ __align__(16) bf16 g_w_h[NW_TOTAL], g_w_l[NW_TOTAL];

__device__ __forceinline__ void bsplit(float x, bf16& h, bf16& l) {
    h = __float2bfloat16(x);
    l = __float2bfloat16(x - __bfloat162float(h));
}
__device__ __forceinline__ uint32_t packbf(bf16 a, bf16 b) {
    uint16_t ua = *(uint16_t*)&a, ub = *(uint16_t*)&b;
    return (uint32_t)ua | ((uint32_t)ub << 16);
}

#define MMA_BF16(c, a, b) \
    asm volatile("mma.sync.aligned.m16n8k16.row.col.f32.bf16.bf16.f32 " \
        "{%0,%1,%2,%3}, {%4,%5,%6,%7}, {%8,%9}, {%0,%1,%2,%3};" \
        : "+f"(c[0]), "+f"(c[1]), "+f"(c[2]), "+f"(c[3]) \
        : "r"(a[0]), "r"(a[1]), "r"(a[2]), "r"(a[3]), "r"(b[0]), "r"(b[1]))

// ============================================================
// Single merged weight hi/lo split
// ============================================================
__global__ void split_all(const float* __restrict__ Wq, const float* __restrict__ Wk,
                          const float* __restrict__ Wv, const float* __restrict__ Wo,
                          const float* __restrict__ f1, const float* __restrict__ f2,
                          bf16* __restrict__ h, bf16* __restrict__ l)
{
    int i = blockIdx.x * 256 + threadIdx.x;
    if (i >= NW_TOTAL) return;
    const float* src; int off;
    if (i < OFF_WO) {
        int m = i / 147456; off = i - m * 147456;
        src = (m == 0) ? Wq : (m == 1) ? Wk : Wv;
    } else if (i < OFF_FC1) { src = Wo; off = i - OFF_WO; }
    else if (i < OFF_FC2)   { src = f1; off = i - OFF_FC1; }
    else                    { src = f2; off = i - OFF_FC2; }
    bsplit(src[off], h[i], l[i]);
}

// ============================================================
// LayerNorm -> bf16 hi/lo (unchanged)
// ============================================================
__global__ void ln_kernel(const float* __restrict__ x,
                          const float* __restrict__ gamma,
                          const float* __restrict__ beta,
                          bf16* __restrict__ tok_h, bf16* __restrict__ tok_l)
{
    int b  = blockIdx.y;
    int l0 = blockIdx.x * 32;
    int lane = threadIdx.x;
    int cy   = threadIdx.y;

    __shared__ float redS [8][32];
    __shared__ float redS2[8][32];
    __shared__ float s_mu[32], s_inv[32];
    __shared__ float buf[64][33];

    float s = 0.f, s2 = 0.f;
    for (int c = cy; c < CC; c += 8) {
        float v = x[((size_t)b*CC + c)*LL + l0 + lane];
        s += v; s2 += v*v;
    }
    redS[cy][lane] = s; redS2[cy][lane] = s2;
    __syncthreads();
    if (cy == 0) {
        float ts = 0.f, ts2 = 0.f;
        #pragma unroll
        for (int i = 0; i < 8; i++) { ts += redS[i][lane]; ts2 += redS2[i][lane]; }
        float mu = ts * (1.0f/384.0f);
        float var = ts2 * (1.0f/384.0f) - mu*mu;
        s_mu[lane] = mu;
        s_inv[lane] = rsqrtf(var + LN_EPS_);
    }
    __syncthreads();

    int tid = cy*32 + lane;
    for (int c0 = 0; c0 < CC; c0 += 64) {
        for (int e = tid; e < 64*32; e += 256) {
            int c = e >> 5, t = e & 31;
            buf[c][t] = x[((size_t)b*CC + c0 + c)*LL + l0 + t];
        }
        __syncthreads();
        for (int e = tid; e < 64*32; e += 256) {
            int c = e & 63, t = e >> 6;
            float v = (buf[c][t] - s_mu[t]) * s_inv[t];
            v = v * gamma[c0 + c] + beta[c0 + c];
            size_t idx = ((size_t)b*LL + l0 + t)*CC + c0 + c;
            bf16 hh, ll;
            bsplit(v, hh, ll);
            tok_h[idx] = hh; tok_l[idx] = ll;
        }
        __syncthreads();
    }
}

// ============================================================
// bf16x3 warp-MMA GEMM (round-6, proven). MODE 2 now fused-QKV.
// ============================================================
template<int MODE>
__global__ __launch_bounds__(256)
void gemm_bf(const bf16* __restrict__ Ah, const bf16* __restrict__ Al,
             const bf16* __restrict__ Wh, const bf16* __restrict__ Wl,
             const float* __restrict__ bias,
             float* __restrict__ Out,
             int M, int N, int K,
             const float* __restrict__ aux,
             bf16* __restrict__ outH, bf16* __restrict__ outL)
{
    __shared__ uint32_t sAh[128][20], sAl[128][20];
    __shared__ uint32_t sBh[64][20],  sBl[64][20];

    const int tid  = threadIdx.x;
    const int m0   = blockIdx.y * 128;
    const int n0   = blockIdx.x * 64;
    const int warp = tid >> 5, lane = tid & 31;
    const int wm   = (warp >> 1) * 32;
    const int wn   = (warp & 1) * 32;
    const int gk   = lane & 3;
    const int gr   = lane >> 2;

    const int ar = tid >> 1, ak = (tid & 1) * 16;
    const int br = tid >> 2, bk = (tid & 3) * 8;

    const bf16* ApH = Ah + (size_t)(m0 + ar) * K + ak;
    const bf16* ApL = Al + (size_t)(m0 + ar) * K + ak;
    const bf16* BpH = Wh + (size_t)(n0 + br) * K + bk;
    const bf16* BpL = Wl + (size_t)(n0 + br) * K + bk;

    uint4 pah0 = *(const uint4*)ApH;
    uint4 pah1 = *(const uint4*)(ApH + 8);
    uint4 pal0 = *(const uint4*)ApL;
    uint4 pal1 = *(const uint4*)(ApL + 8);
    uint4 pbh  = *(const uint4*)BpH;
    uint4 pbl  = *(const uint4*)BpL;

    float acc[2][4][4];
    #pragma unroll
    for (int mi = 0; mi < 2; mi++)
        #pragma unroll
        for (int nj = 0; nj < 4; nj++)
            #pragma unroll
            for (int r = 0; r < 4; r++) acc[mi][nj][r] = 0.f;

    const int acol = (tid & 1) * 8;
    const int bcol = (tid & 3) * 4;

    for (int k0 = 0; k0 < K; k0 += 32) {
        *(uint4*)&sAh[ar][acol]     = pah0;
        *(uint4*)&sAh[ar][acol + 4] = pah1;
        *(uint4*)&sAl[ar][acol]     = pal0;
        *(uint4*)&sAl[ar][acol + 4] = pal1;
        *(uint4*)&sBh[br][bcol]     = pbh;
        *(uint4*)&sBl[br][bcol]     = pbl;
        __syncthreads();

        if (k0 + 32 < K) {
            ApH += 32; ApL += 32; BpH += 32; BpL += 32;
            pah0 = *(const uint4*)ApH;
            pah1 = *(const uint4*)(ApH + 8);
            pal0 = *(const uint4*)ApL;
            pal1 = *(const uint4*)(ApL + 8);
            pbh  = *(const uint4*)BpH;
            pbl  = *(const uint4*)BpL;
        }

        #pragma unroll
        for (int ks = 0; ks < 2; ks++) {
            const int kb = ks*8 + gk;
            uint32_t ah[2][4], al_[2][4];
            #pragma unroll
            for (int mi = 0; mi < 2; mi++) {
                int mr = wm + mi*16 + gr;
                ah[mi][0]  = sAh[mr    ][kb];
                ah[mi][1]  = sAh[mr + 8][kb];
                ah[mi][2]  = sAh[mr    ][kb + 4];
                ah[mi][3]  = sAh[mr + 8][kb + 4];
                al_[mi][0] = sAl[mr    ][kb];
                al_[mi][1] = sAl[mr + 8][kb];
                al_[mi][2] = sAl[mr    ][kb + 4];
                al_[mi][3] = sAl[mr + 8][kb + 4];
            }
            #pragma unroll
            for (int nj = 0; nj < 4; nj++) {
                int nc = wn + nj*8 + gr;
                uint32_t bh[2], bl[2];
                bh[0] = sBh[nc][kb];
                bh[1] = sBh[nc][kb + 4];
                bl[0] = sBl[nc][kb];
                bl[1] = sBl[nc][kb + 4];
                #pragma unroll
                for (int mi = 0; mi < 2; mi++) {
                    MMA_BF16(acc[mi][nj], ah[mi],  bh);
                    MMA_BF16(acc[mi][nj], al_[mi], bh);
                    MMA_BF16(acc[mi][nj], ah[mi],  bl);
                }
            }
        }
        __syncthreads();
    }

    #pragma unroll
    for (int mi = 0; mi < 2; mi++) {
        #pragma unroll
        for (int nj = 0; nj < 4; nj++) {
            #pragma unroll
            for (int r = 0; r < 4; r++) {
                int row = m0 + wm + mi*16 + gr + ((r & 2) ? 8 : 0);
                int col = n0 + wn + nj*8 + 2*gk + (r & 1);
                int b = row >> 10, l = row & 1023;
                float v = acc[mi][nj][r] + (bias ? bias[col] : 0.f);
                if (MODE == 2) {
                    // fused QKV: col in [0,1152)
                    int mat = col / 384;
                    int cm  = col - mat * 384;
                    int h = cm / 48, d = cm % 48;
                    Out[(size_t)mat * (MM*CC)
                        + (size_t)(((b*8 + h) * 1024) + l) * 48 + d] = v;
                } else if (MODE == 3) {
                    v += aux[(size_t)(b*384 + col) * 1024 + l];
                    size_t idx = (size_t)row * 384 + col;
                    Out[idx] = v;
                    bf16 hh, ll;
                    bsplit(v, hh, ll);
                    outH[idx] = hh; outL[idx] = ll;
                } else if (MODE == 1) {
                    v = 0.5f * v * (1.0f + erff(v * 0.70710678118654752f));
                    size_t idx = (size_t)row * N + col;
                    bf16 hh, ll;
                    bsplit(v, hh, ll);
                    outH[idx] = hh; outL[idx] = ll;
                } else { // MODE 4
                    Out[(size_t)(b*384 + col) * 1024 + l] =
                        v + aux[(size_t)row * 384 + col];
                }
            }
        }
    }
}

// ============================================================
// FlashAttention-2 style bf16x3 warp-MMA attention.
// block = 256 thr (8 warps), 128 q-rows/block, 64 keys/chunk.
// grid (L/128, B*NH).
// Warp w owns rows q0+16w+{gid,gid+8}; softmax state in regs
// (redundant across quad lanes); S frags reused as P A-frags.
// ============================================================
__global__ __launch_bounds__(256, 1)
void attn_mma(const float* __restrict__ q,
              const float* __restrict__ k,
              const float* __restrict__ v,
              const float* __restrict__ rel_bias,
              bf16* __restrict__ attn_h, bf16* __restrict__ attn_l)
{
    const int b  = blockIdx.y >> 3;
    const int h  = blockIdx.y & 7;
    const int q0 = blockIdx.x * 128;
    const int tid  = threadIdx.x;
    const int warp = tid >> 5, lane = tid & 31;
    const int gid  = lane >> 2;       // 0..7
    const int tig  = lane & 3;        // 0..3

    __shared__ uint32_t sKh[64][25], sKl[64][25];   // [key][dpair]
    __shared__ uint32_t sVh[48][33], sVl[48][33];   // [d][mpair]

    const float* qbase = q + (size_t)((b*NHH + h) * LL) * DKK;
    const float* kbase = k + (size_t)((b*NHH + h) * LL) * DKK;
    const float* vbase = v + (size_t)((b*NHH + h) * LL) * DKK;
    const float* biasrow = rel_bias + (size_t)h * NBIAS_;

    const int qrow0 = q0 + warp*16 + gid;    // global l of row A
    const int qrow1 = qrow0 + 8;             // row B
    const int ly0 = qrow0 >> 5, lx0 = qrow0 & 31;
    const int ly1 = qrow1 >> 5, lx1 = qrow1 & 31;

    // ---- load Q fragments (hi/lo), 3 ksteps of k16 over DK=48 ----
    uint32_t qh[3][4], ql[3][4];
    #pragma unroll
    for (int kp = 0; kp < 3; kp++) {
        int d0 = 16*kp + 2*tig;
        #pragma unroll
        for (int rr = 0; rr < 2; rr++) {       // row gid / gid+8
            int row = rr ? qrow1 : qrow0;
            float2 e0 = *(const float2*)&qbase[(size_t)row*48 + d0];
            float2 e1 = *(const float2*)&qbase[(size_t)row*48 + d0 + 8];
            bf16 h0, l0, h1, l1;
            bsplit(e0.x, h0, l0); bsplit(e0.y, h1, l1);
            qh[kp][rr]   = packbf(h0, h1);  ql[kp][rr]   = packbf(l0, l1);
            bsplit(e1.x, h0, l0); bsplit(e1.y, h1, l1);
            qh[kp][rr+2] = packbf(h0, h1);  ql[kp][rr+2] = packbf(l0, l1);
        }
    }

    float m0r = -1e30f, m1r = -1e30f, s0r = 0.f, s1r = 0.f;
    float o[6][4];
    #pragma unroll
    for (int nt = 0; nt < 6; nt++)
        #pragma unroll
        for (int r = 0; r < 4; r++) o[nt][r] = 0.f;

    for (int mc = 0; mc < LL; mc += 64) {
        __syncthreads();   // protect buffers from previous chunk's readers

        // ---- stage K (pack along d) ----
        for (int e = tid; e < 64*24; e += 256) {
            int r = e / 24, dp = e % 24;
            float2 kv = *(const float2*)&kbase[(size_t)(mc + r)*48 + 2*dp];
            bf16 h0, l0, h1, l1;
            bsplit(kv.x, h0, l0); bsplit(kv.y, h1, l1);
            sKh[r][dp] = packbf(h0, h1);
            sKl[r][dp] = packbf(l0, l1);
        }
        // ---- stage V (pack along m) ----
        for (int e = tid; e < 48*32; e += 256) {
            int d = e % 48, mp = e / 48;
            float v0 = vbase[(size_t)(mc + 2*mp    )*48 + d];
            float v1 = vbase[(size_t)(mc + 2*mp + 1)*48 + d];
            bf16 h0, l0, h1, l1;
            bsplit(v0, h0, l0); bsplit(v1, h1, l1);
            sVh[d][mp] = packbf(h0, h1);
            sVl[d][mp] = packbf(l0, l1);
        }
        __syncthreads();

        // ---- S = Q K^T (bf16x3), 8 n-tiles of 8 keys ----
        float sc[8][4];
        #pragma unroll
        for (int t = 0; t < 8; t++)
            #pragma unroll
            for (int r = 0; r < 4; r++) sc[t][r] = 0.f;

        #pragma unroll
        for (int kp = 0; kp < 3; kp++) {
            #pragma unroll
            for (int t = 0; t < 8; t++) {
                int key = 8*t + gid;
                int dp  = 8*kp + tig;
                uint32_t bh[2] = { sKh[key][dp], sKh[key][dp + 4] };
                uint32_t bl[2] = { sKl[key][dp], sKl[key][dp + 4] };
                MMA_BF16(sc[t], qh[kp], bh);
                MMA_BF16(sc[t], ql[kp], bh);
                MMA_BF16(sc[t], qh[kp], bl);
            }
        }

        // ---- bias + row max ----
        float rm0 = -1e30f, rm1 = -1e30f;
        #pragma unroll
        for (int t = 0; t < 8; t++) {
            int ma = mc + 8*t + 2*tig, mb = ma + 1;
            int may = ma >> 5, max_ = ma & 31;
            int mby = mb >> 5, mbx = mb & 31;
            sc[t][0] += biasrow[(may - ly0 + 32)*32 + (max_ - lx0 + 32)];
            sc[t][1] += biasrow[(mby - ly0 + 32)*32 + (mbx - lx0 + 32)];
            sc[t][2] += biasrow[(may - ly1 + 32)*32 + (max_ - lx1 + 32)];
            sc[t][3] += biasrow[(mby - ly1 + 32)*32 + (mbx - lx1 + 32)];
            rm0 = fmaxf(rm0, fmaxf(sc[t][0], sc[t][1]));
            rm1 = fmaxf(rm1, fmaxf(sc[t][2], sc[t][3]));
        }
        rm0 = fmaxf(rm0, __shfl_xor_sync(0xffffffffu, rm0, 1));
        rm0 = fmaxf(rm0, __shfl_xor_sync(0xffffffffu, rm0, 2));
        rm1 = fmaxf(rm1, __shfl_xor_sync(0xffffffffu, rm1, 1));
        rm1 = fmaxf(rm1, __shfl_xor_sync(0xffffffffu, rm1, 2));

        float nm0 = fmaxf(m0r, rm0), nm1 = fmaxf(m1r, rm1);
        float al0 = __expf(m0r - nm0), al1 = __expf(m1r - nm1);
        m0r = nm0; m1r = nm1;

        // ---- exp + pack P hi/lo as A-fragments ----
        uint32_t ph01[8], ph23[8], pl01[8], pl23[8];
        float ps0 = 0.f, ps1 = 0.f;
        #pragma unroll
        for (int t = 0; t < 8; t++) {
            float p0 = __expf(sc[t][0] - nm0);
            float p1 = __expf(sc[t][1] - nm0);
            float p2 = __expf(sc[t][2] - nm1);
            float p3 = __expf(sc[t][3] - nm1);
            ps0 += p0 + p1; ps1 += p2 + p3;
            bf16 h0, l0, h1, l1;
            bsplit(p0, h0, l0); bsplit(p1, h1, l1);
            ph01[t] = packbf(h0, h1); pl01[t] = packbf(l0, l1);
            bsplit(p2, h0, l0); bsplit(p3, h1, l1);
            ph23[t] = packbf(h0, h1); pl23[t] = packbf(l0, l1);
        }
        ps0 += __shfl_xor_sync(0xffffffffu, ps0, 1);
        ps0 += __shfl_xor_sync(0xffffffffu, ps0, 2);
        ps1 += __shfl_xor_sync(0xffffffffu, ps1, 1);
        ps1 += __shfl_xor_sync(0xffffffffu, ps1, 2);
        s0r = s0r * al0 + ps0;
        s1r = s1r * al1 + ps1;

        // ---- rescale O ----
        #pragma unroll
        for (int nt = 0; nt < 6; nt++) {
            o[nt][0] *= al0; o[nt][1] *= al0;
            o[nt][2] *= al1; o[nt][3] *= al1;
        }

        // ---- O += P V (bf16x3), 4 ksteps of 16 keys, 6 n-tiles of 8 d ----
        #pragma unroll
        for (int kp = 0; kp < 4; kp++) {
            uint32_t ah[4]  = { ph01[2*kp], ph23[2*kp], ph01[2*kp+1], ph23[2*kp+1] };
            uint32_t alo[4] = { pl01[2*kp], pl23[2*kp], pl01[2*kp+1], pl23[2*kp+1] };
            #pragma unroll
            for (int nt = 0; nt < 6; nt++) {
                int d  = 8*nt + gid;
                int mp = 8*kp + tig;
                uint32_t bh[2] = { sVh[d][mp], sVh[d][mp + 4] };
                uint32_t bl[2] = { sVl[d][mp], sVl[d][mp + 4] };
                MMA_BF16(o[nt], ah,  bh);
                MMA_BF16(o[nt], alo, bh);
                MMA_BF16(o[nt], ah,  bl);
            }
        }
    }

    // ---- epilogue: normalize + write bf16 hi/lo (packed u32 stores) ----
    float inv0 = 1.0f / s0r, inv1 = 1.0f / s1r;
    uint32_t* outh32 = (uint32_t*)attn_h;
    uint32_t* outl32 = (uint32_t*)attn_l;
    #pragma unroll
    for (int nt = 0; nt < 6; nt++) {
        int d = 8*nt + 2*tig;
        size_t i0 = ((size_t)(b*LL + qrow0) * 384 + h*48 + d) >> 1;
        size_t i1 = ((size_t)(b*LL + qrow1) * 384 + h*48 + d) >> 1;
        bf16 h0, l0, h1, l1;
        bsplit(o[nt][0]*inv0, h0, l0); bsplit(o[nt][1]*inv0, h1, l1);
        outh32[i0] = packbf(h0, h1);   outl32[i0] = packbf(l0, l1);
        bsplit(o[nt][2]*inv1, h0, l0); bsplit(o[nt][3]*inv1, h1, l1);
        outh32[i1] = packbf(h0, h1);   outl32[i1] = packbf(l0, l1);
    }
}

// ============================================================
// launch
// ============================================================
extern "C" void kernel_launch(void* const* d_in, const int* in_sizes, int n_in,
                              void* d_out, int out_size)
{
    (void)in_sizes; (void)n_in; (void)out_size;
    const float* x        = (const float*)d_in[0];
    const float* gamma    = (const float*)d_in[1];
    const float* beta     = (const float*)d_in[2];
    const float* Wq       = (const float*)d_in[3];
    const float* Wk       = (const float*)d_in[4];
    const float* Wv       = (const float*)d_in[5];
    const float* Wo       = (const float*)d_in[6];
    const float* bo       = (const float*)d_in[7];
    const float* rel_bias = (const float*)d_in[8];
    const float* fc1_w    = (const float*)d_in[9];
    const float* fc1_b    = (const float*)d_in[10];
    const float* fc2_w    = (const float*)d_in[11];
    const float* fc2_b    = (const float*)d_in[12];
    float* out = (float*)d_out;

    bf16 *tok_h, *tok_l, *attn_h, *attn_l, *ytok_h, *ytok_l, *u1_h, *u1_l, *w_h, *w_l;
    float *qkv, *ytok;
    cudaGetSymbolAddress((void**)&tok_h,  g_tok_h);
    cudaGetSymbolAddress((void**)&tok_l,  g_tok_l);
    cudaGetSymbolAddress((void**)&qkv,    g_qkv);
    cudaGetSymbolAddress((void**)&attn_h, g_attn_h);
    cudaGetSymbolAddress((void**)&attn_l, g_attn_l);
    cudaGetSymbolAddress((void**)&ytok,   g_ytok);
    cudaGetSymbolAddress((void**)&ytok_h, g_ytok_h);
    cudaGetSymbolAddress((void**)&ytok_l, g_ytok_l);
    cudaGetSymbolAddress((void**)&u1_h,   g_u1_h);
    cudaGetSymbolAddress((void**)&u1_l,   g_u1_l);
    cudaGetSymbolAddress((void**)&w_h,    g_w_h);
    cudaGetSymbolAddress((void**)&w_l,    g_w_l);

    float* q = qkv;
    float* k = qkv + (size_t)MM*CC;
    float* v = qkv + 2*(size_t)MM*CC;

    const int M = MM;

    split_all<<<(NW_TOTAL + 255)/256, 256>>>(Wq, Wk, Wv, Wo, fc1_w, fc2_w, w_h, w_l);

    ln_kernel<<<dim3(LL/32, BB), dim3(32, 8)>>>(x, gamma, beta, tok_h, tok_l);

    // fused QKV: N = 1152 (Wq|Wk|Wv contiguous in split pool)
    gemm_bf<2><<<dim3(1152/64, M/128), 256>>>(tok_h, tok_l, w_h+OFF_WQ, w_l+OFF_WQ,
                                              nullptr, qkv, M, 1152, 384, nullptr, nullptr, nullptr);

    attn_mma<<<dim3(LL/128, BB*NHH), 256>>>(q, k, v, rel_bias, attn_h, attn_l);

    gemm_bf<3><<<dim3(384/64,  M/128), 256>>>(attn_h, attn_l, w_h+OFF_WO, w_l+OFF_WO,
                                              bo, ytok, M, 384, 384, x, ytok_h, ytok_l);
    gemm_bf<1><<<dim3(1536/64, M/128), 256>>>(ytok_h, ytok_l, w_h+OFF_FC1, w_l+OFF_FC1,
                                              fc1_b, nullptr, M, 1536, 384, nullptr, u1_h, u1_l);
    gemm_bf<4><<<dim3(384/64,  M/128), 256>>>(u1_h, u1_l, w_h+OFF_FC2, w_l+OFF_FC2,
                                              fc2_b, out, M, 384, 1536, ytok, nullptr, nullptr);
}